// round 11
// baseline (speedup 1.0000x reference)
#include <cuda_runtime.h>
#include <math.h>

// Problem constants
#define BB 64
#define TT 512
#define II 1024
#define HH 1024

#define NB_CTAS 128
#define RNN_THREADS 256

// ---------------- device scratch ----------------
__device__ float g_h[3][BB * HH];                 // triple-buffered hidden state (tf32-rounded bits)
__device__ __align__(512) unsigned g_wf[4 * 32];  // write flags: h_t stored
__device__ __align__(512) unsigned g_rf[4 * 32];  // read flags: h_{t-1} staged

// ---------------- helpers ----------------
__device__ __forceinline__ unsigned f2tf32(float x) {
    unsigned r;
    asm("cvt.rna.tf32.f32 %0, %1;" : "=r"(r) : "f"(x));
    return r;
}

__device__ __forceinline__ void ldmat_x4(unsigned* r, unsigned addr) {
    asm volatile("ldmatrix.sync.aligned.m8n8.x4.shared.b16 {%0,%1,%2,%3}, [%4];"
                 : "=r"(r[0]), "=r"(r[1]), "=r"(r[2]), "=r"(r[3]) : "r"(addr));
}

__device__ __forceinline__ void mma_tf32(float* c, const unsigned* a, unsigned b0, unsigned b1) {
    asm volatile(
        "mma.sync.aligned.m16n8k8.row.col.f32.tf32.tf32.f32 "
        "{%0,%1,%2,%3},{%4,%5,%6,%7},{%8,%9},{%0,%1,%2,%3};"
        : "+f"(c[0]), "+f"(c[1]), "+f"(c[2]), "+f"(c[3])
        : "r"(a[0]), "r"(a[1]), "r"(a[2]), "r"(a[3]), "r"(b0), "r"(b1));
}

__device__ __forceinline__ unsigned ld_acq(const unsigned* p) {
    unsigned v;
    asm volatile("ld.acquire.gpu.global.u32 %0, [%1];" : "=r"(v) : "l"(p));
    return v;
}

__device__ __forceinline__ void st_rel(unsigned* p, unsigned v) {
    asm volatile("st.release.gpu.global.u32 [%0], %1;" :: "l"(p), "r"(v));
}

// ---------------- init ----------------
__global__ void init_kernel(const float* __restrict__ h0) {
    int i = blockIdx.x * blockDim.x + threadIdx.x;
    if (i < BB * HH) g_h[2][i] = __uint_as_float(f2tf32(h0[i]));  // h_{-1} in buf 2, pre-rounded
    if (i < 128) { g_wf[i] = 0u; g_rf[i] = 0u; }
}

// ---------------- phase 1: xp = x @ W_ih^T + b_ih  (tf32 mma) -------------
__global__ void __launch_bounds__(256) gemm_xw_mma(
    const float* __restrict__ A,    // x [M][K]
    const float* __restrict__ W,    // W_ih [N][K]
    const float* __restrict__ bias, // [N]
    float* __restrict__ C)          // [M][N]
{
    __shared__ unsigned As[128 * 32];
    __shared__ unsigned Ws[128 * 32];

    const int tid  = threadIdx.x;
    const int lane = tid & 31;
    const int warp = tid >> 5;
    const int wm   = warp & 1;
    const int wn   = warp >> 1;
    const int n0   = blockIdx.x * 128;
    const int m0   = blockIdx.y * 128;

    const unsigned AsB = (unsigned)__cvta_generic_to_shared(As);
    const unsigned WsB = (unsigned)__cvta_generic_to_shared(Ws);

    float c[4][4][4] = {};

    int lr[4], lg[4];
    size_t aoff[4], woff[4];
#pragma unroll
    for (int i = 0; i < 4; i++) {
        int idx = tid + i * 256;
        lr[i] = idx >> 3;
        lg[i] = idx & 7;
        aoff[i] = (size_t)(m0 + lr[i]) * II + lg[i] * 4;
        woff[i] = (size_t)(n0 + lr[i]) * II + lg[i] * 4;
    }

    float4 ra[4], rw[4];
#pragma unroll
    for (int i = 0; i < 4; i++) {
        ra[i] = *(const float4*)(A + aoff[i]);
        rw[i] = *(const float4*)(W + woff[i]);
    }

    for (int kc = 0; kc < 32; kc++) {
        __syncthreads();
#pragma unroll
        for (int i = 0; i < 4; i++) {
            uint4 ua = { f2tf32(ra[i].x), f2tf32(ra[i].y), f2tf32(ra[i].z), f2tf32(ra[i].w) };
            uint4 uw = { f2tf32(rw[i].x), f2tf32(rw[i].y), f2tf32(rw[i].z), f2tf32(rw[i].w) };
            int off = lr[i] * 32 + ((lg[i] ^ (lr[i] & 7)) << 2);
            *(uint4*)&As[off] = ua;
            *(uint4*)&Ws[off] = uw;
        }
        __syncthreads();

        if (kc + 1 < 32) {
            int k0 = (kc + 1) * 32;
#pragma unroll
            for (int i = 0; i < 4; i++) {
                ra[i] = *(const float4*)(A + aoff[i] + k0);
                rw[i] = *(const float4*)(W + woff[i] + k0);
            }
        }

#pragma unroll
        for (int ks = 0; ks < 4; ks++) {
            unsigned a[4][4], b[4][2];
#pragma unroll
            for (int mi = 0; mi < 4; mi++) {
                int r = wm * 64 + mi * 16 + ((lane >> 3) & 1) * 8 + (lane & 7);
                int g = ks * 2 + (lane >> 4);
                ldmat_x4(a[mi], AsB + (unsigned)(r * 32 + ((g ^ (r & 7)) << 2)) * 4u);
            }
#pragma unroll
            for (int p = 0; p < 2; p++) {
                int r = wn * 32 + p * 16 + (lane >> 4) * 8 + (lane & 7);
                int g = ks * 2 + ((lane >> 3) & 1);
                unsigned t[4];
                ldmat_x4(t, WsB + (unsigned)(r * 32 + ((g ^ (r & 7)) << 2)) * 4u);
                b[p * 2 + 0][0] = t[0]; b[p * 2 + 0][1] = t[1];
                b[p * 2 + 1][0] = t[2]; b[p * 2 + 1][1] = t[3];
            }
#pragma unroll
            for (int mi = 0; mi < 4; mi++)
#pragma unroll
                for (int ni = 0; ni < 4; ni++)
                    mma_tf32(c[mi][ni], a[mi], b[ni][0], b[ni][1]);
        }
    }

#pragma unroll
    for (int mi = 0; mi < 4; mi++) {
        int r = m0 + wm * 64 + mi * 16 + (lane >> 2);
#pragma unroll
        for (int ni = 0; ni < 4; ni++) {
            int col = n0 + wn * 32 + ni * 8 + (lane & 3) * 2;
            float2 bv = *(const float2*)&bias[col];
            float2 o0 = { c[mi][ni][0] + bv.x, c[mi][ni][1] + bv.y };
            float2 o1 = { c[mi][ni][2] + bv.x, c[mi][ni][3] + bv.y };
            *(float2*)&C[(size_t)r * HH + col]       = o0;
            *(float2*)&C[(size_t)(r + 8) * HH + col] = o1;
        }
    }
}

// ---------------- phase 2: persistent recurrent scan (tf32 mma) ----------
// 128 CTAs = 32 H-tiles (32 cols) x 4 B-tiles (16 rows).
// 8 warps = 4 n-tiles (8 cols) x 2 k-halves (512 k). W fragments hoisted to
// registers (loaded once). Triple-buffered h + split write/read flags.
__global__ void __launch_bounds__(RNN_THREADS, 1) rnn_scan_mma(
    const float* __restrict__ W_hh,
    const float* __restrict__ b_hh,
    float* __restrict__ out)
{
    extern __shared__ unsigned smbuf[];
    unsigned* Wstage = smbuf;             // [32][1024] tf32 swizzled (one-shot)
    unsigned* Ht     = smbuf + 32 * 1024; // [16][1024] tf32 swizzled
    float* red = (float*)(smbuf + 48 * 1024); // [2][16][36]

    const int tid  = threadIdx.x;
    const int lane = tid & 31;
    const int warp = tid >> 5;
    const int nt   = warp & 3;   // n tile: 8 cols
    const int kh   = warp >> 2;  // k half: 512 k
    const int bid  = blockIdx.x;
    const int ht   = bid & 31;
    const int bt   = bid >> 5;

    const unsigned HtB = (unsigned)__cvta_generic_to_shared(Ht);
    const unsigned WsB = (unsigned)__cvta_generic_to_shared(Wstage);

    // ---- stage W_hh slice into smem (tf32, swizzled), once ----
#pragma unroll
    for (int i = 0; i < 32; i++) {
        float4 v = *(const float4*)(W_hh + (((size_t)(ht * 32 + i)) << 10) + tid * 4);
        uint4 u = { f2tf32(v.x), f2tf32(v.y), f2tf32(v.z), f2tf32(v.w) };
        *(uint4*)&Wstage[i * 1024 + ((tid ^ (i & 7)) << 2)] = u;
    }
    __syncthreads();

    // ---- hoist this warp's B fragments into registers (32 k16-chunks) ----
    unsigned bw[128];
#pragma unroll
    for (int s2 = 0; s2 < 32; s2++) {
        int r = nt * 8 + (lane & 7);
        int g = kh * 128 + s2 * 4 + (lane >> 3);
        ldmat_x4(&bw[s2 * 4], WsB + (unsigned)(r * 1024 + ((g ^ (r & 7)) << 2)) * 4u);
    }

    // ---- per-thread epilogue constants (2 adjacent outputs/thread) ----
    const int erow = tid >> 4;
    const int ecol = (2 * tid) & 31;
    const int gb   = bt * 16 + erow;
    const int gc   = ht * 32 + ecol;
    const float2 bh = *(const float2*)&b_hh[gc];
    float* oPtr = out + (size_t)gb * TT * HH + gc;
    const size_t hOff = (size_t)gb * HH + gc;

    unsigned* wfGrp = &g_wf[bt * 32];
    unsigned* rfGrp = &g_rf[bt * 32];
    unsigned* myWf  = &g_wf[bt * 32 + ht];
    unsigned* myRf  = &g_rf[bt * 32 + ht];

    // dump constants
    const int rowb = lane >> 2;
    const int colg = nt * 8 + 2 * (lane & 3);

    int rb = 2, wb = 0;  // read/write buffer indices (t-1 mod 3 / t mod 3)

    for (int t = 0; t < TT; ++t) {
        const float* hRead = &g_h[0][0] + (size_t)rb * (BB * HH) + (size_t)bt * 16 * HH;

        // ---- xp prefetch (independent; hides DRAM under the wait) ----
        float2 xp = __ldcg((const float2*)(oPtr + (size_t)t * HH));

        // ---- wait: peers wrote h_{t-1} (wf>=t) and staged h_{t-3} (rf>=t-1) ----
        if (t > 0) {
            const unsigned tw = (unsigned)t;
            const unsigned tr = (t >= 2) ? (unsigned)(t - 1) : 0u;
            if (warp == 0) {
                while (true) {
                    unsigned wv = ld_acq(&wfGrp[lane]);
                    unsigned rv = ld_acq(&rfGrp[lane]);
                    if (__all_sync(0xffffffffu, (wv >= tw) && (rv >= tr))) break;
                }
            }
            __syncthreads();
        }

        // ---- stage h_{t-1} tile (already tf32 bits; pure copy + swizzle) ----
#pragma unroll
        for (int i = 0; i < 16; i++) {
            float4 v = __ldcg((const float4*)(hRead + ((size_t)i << 10) + tid * 4));
            *(float4*)&Ht[i * 1024 + ((tid ^ (i & 7)) << 2)] = v;
        }
        __syncthreads();
        if (tid == 0) st_rel(myRf, (unsigned)(t + 1));  // staged step t

        // ---- mma over this warp's 512-k half, n8 tile, W from registers ----
        float c0[4] = {}, c1[4] = {};
#pragma unroll
        for (int s2 = 0; s2 < 32; s2++) {
            int g0 = kh * 128 + s2 * 4;
            unsigned a0[4], a1[4];
            int r = (lane & 7) + ((lane >> 3) & 1) * 8;
            int g = g0 + (lane >> 4);
            ldmat_x4(a0, HtB + (unsigned)(r * 1024 + ((g ^ (r & 7)) << 2)) * 4u);
            g += 2;
            ldmat_x4(a1, HtB + (unsigned)(r * 1024 + ((g ^ (r & 7)) << 2)) * 4u);
            mma_tf32(c0, a0, bw[s2 * 4 + 0], bw[s2 * 4 + 1]);
            mma_tf32(c1, a1, bw[s2 * 4 + 2], bw[s2 * 4 + 3]);
        }

        // ---- dump 2-way split-K partials ----
        red[kh * 576 + rowb * 36 + colg]           = c0[0] + c1[0];
        red[kh * 576 + rowb * 36 + colg + 1]       = c0[1] + c1[1];
        red[kh * 576 + (rowb + 8) * 36 + colg]     = c0[2] + c1[2];
        red[kh * 576 + (rowb + 8) * 36 + colg + 1] = c0[3] + c1[3];
        __syncthreads();

        // ---- reduce + epilogue (all 256 threads, 2 outputs each) ----
        float s0 = xp.x + bh.x + red[erow * 36 + ecol]     + red[576 + erow * 36 + ecol];
        float s1 = xp.y + bh.y + red[erow * 36 + ecol + 1] + red[576 + erow * 36 + ecol + 1];
        float2 hv = { tanhf(s0), tanhf(s1) };

        *(float2*)(oPtr + (size_t)t * HH) = hv;
        float2 hs = { __uint_as_float(f2tf32(hv.x)), __uint_as_float(f2tf32(hv.y)) };
        __stcg((float2*)(&g_h[0][0] + (size_t)wb * (BB * HH) + hOff), hs);

        __syncthreads();
        if (tid == 0) st_rel(myWf, (unsigned)(t + 1));  // h_t visible

        rb = wb;
        wb = (wb == 2) ? 0 : (wb + 1);
    }
}

// ---------------- launch ----------------
extern "C" void kernel_launch(void* const* d_in, const int* in_sizes, int n_in,
                              void* d_out, int out_size) {
    const float* x    = (const float*)d_in[0];
    const float* h0   = (const float*)d_in[1];
    const float* W_ih = (const float*)d_in[2];
    const float* b_ih = (const float*)d_in[3];
    const float* W_hh = (const float*)d_in[4];
    const float* b_hh = (const float*)d_in[5];
    float* out = (float*)d_out;

    init_kernel<<<(BB * HH + 255) / 256, 256>>>(h0);

    dim3 g1(HH / 128, (BB * TT) / 128);
    gemm_xw_mma<<<g1, 256>>>(x, W_ih, b_ih, out);

    const int smem_bytes = (48 * 1024) * 4 + 2 * 576 * 4;  // 201216 B
    cudaFuncSetAttribute(rnn_scan_mma,
                         cudaFuncAttributeMaxDynamicSharedMemorySize, smem_bytes);
    rnn_scan_mma<<<NB_CTAS, RNN_THREADS, smem_bytes>>>(W_hh, b_hh, out);
}

// round 12
// speedup vs baseline: 1.4111x; 1.4111x over previous
#include <cuda_runtime.h>
#include <math.h>

// Problem constants
#define BB 64
#define TT 512
#define II 1024
#define HH 1024

#define NB_CTAS 128
#define RNN_THREADS 256

// ---------------- device scratch ----------------
__device__ float g_h[2][BB * HH];                       // ping-pong hidden state (tf32-rounded bits)
__device__ __align__(512) unsigned g_cnt[4][4][32];     // per-bt-group, 4 sub-counters 128B apart

// ---------------- helpers ----------------
__device__ __forceinline__ unsigned f2tf32(float x) {
    unsigned r;
    asm("cvt.rna.tf32.f32 %0, %1;" : "=r"(r) : "f"(x));
    return r;
}

__device__ __forceinline__ void ldmat_x4(unsigned* r, unsigned addr) {
    asm volatile("ldmatrix.sync.aligned.m8n8.x4.shared.b16 {%0,%1,%2,%3}, [%4];"
                 : "=r"(r[0]), "=r"(r[1]), "=r"(r[2]), "=r"(r[3]) : "r"(addr));
}

__device__ __forceinline__ void mma_tf32(float* c, const unsigned* a, unsigned b0, unsigned b1) {
    asm volatile(
        "mma.sync.aligned.m16n8k8.row.col.f32.tf32.tf32.f32 "
        "{%0,%1,%2,%3},{%4,%5,%6,%7},{%8,%9},{%0,%1,%2,%3};"
        : "+f"(c[0]), "+f"(c[1]), "+f"(c[2]), "+f"(c[3])
        : "r"(a[0]), "r"(a[1]), "r"(a[2]), "r"(a[3]), "r"(b0), "r"(b1));
}

__device__ __forceinline__ unsigned ld_acq(const unsigned* p) {
    unsigned v;
    asm volatile("ld.acquire.gpu.global.u32 %0, [%1];" : "=r"(v) : "l"(p));
    return v;
}

// ---------------- init ----------------
__global__ void init_kernel(const float* __restrict__ h0) {
    int i = blockIdx.x * blockDim.x + threadIdx.x;
    if (i < BB * HH) g_h[0][i] = __uint_as_float(f2tf32(h0[i]));  // pre-rounded
    if (i < 512) ((unsigned*)g_cnt)[i] = 0u;
}

// ---------------- phase 1: xp = x @ W_ih^T + b_ih  (tf32 mma) -------------
// CTA tile 128(M) x 128(N), k-chunk 32. 8 warps (2m x 4n), warp tile 64x32.
__global__ void __launch_bounds__(256) gemm_xw_mma(
    const float* __restrict__ A,    // x [M][K]
    const float* __restrict__ W,    // W_ih [N][K]
    const float* __restrict__ bias, // [N]
    float* __restrict__ C)          // [M][N]
{
    __shared__ unsigned As[128 * 32];
    __shared__ unsigned Ws[128 * 32];

    const int tid  = threadIdx.x;
    const int lane = tid & 31;
    const int warp = tid >> 5;
    const int wm   = warp & 1;   // 0..1
    const int wn   = warp >> 1;  // 0..3
    const int n0   = blockIdx.x * 128;
    const int m0   = blockIdx.y * 128;

    const unsigned AsB = (unsigned)__cvta_generic_to_shared(As);
    const unsigned WsB = (unsigned)__cvta_generic_to_shared(Ws);

    float c[4][4][4] = {};

    int lr[4], lg[4];
    size_t aoff[4], woff[4];
#pragma unroll
    for (int i = 0; i < 4; i++) {
        int idx = tid + i * 256;
        lr[i] = idx >> 3;
        lg[i] = idx & 7;
        aoff[i] = (size_t)(m0 + lr[i]) * II + lg[i] * 4;
        woff[i] = (size_t)(n0 + lr[i]) * II + lg[i] * 4;
    }

    float4 ra[4], rw[4];
#pragma unroll
    for (int i = 0; i < 4; i++) {
        ra[i] = *(const float4*)(A + aoff[i]);
        rw[i] = *(const float4*)(W + woff[i]);
    }

    for (int kc = 0; kc < 32; kc++) {
        __syncthreads();
#pragma unroll
        for (int i = 0; i < 4; i++) {
            uint4 ua = { f2tf32(ra[i].x), f2tf32(ra[i].y), f2tf32(ra[i].z), f2tf32(ra[i].w) };
            uint4 uw = { f2tf32(rw[i].x), f2tf32(rw[i].y), f2tf32(rw[i].z), f2tf32(rw[i].w) };
            int off = lr[i] * 32 + ((lg[i] ^ (lr[i] & 7)) << 2);
            *(uint4*)&As[off] = ua;
            *(uint4*)&Ws[off] = uw;
        }
        __syncthreads();

        if (kc + 1 < 32) {
            int k0 = (kc + 1) * 32;
#pragma unroll
            for (int i = 0; i < 4; i++) {
                ra[i] = *(const float4*)(A + aoff[i] + k0);
                rw[i] = *(const float4*)(W + woff[i] + k0);
            }
        }

#pragma unroll
        for (int ks = 0; ks < 4; ks++) {
            unsigned a[4][4], b[4][2];
#pragma unroll
            for (int mi = 0; mi < 4; mi++) {
                int r = wm * 64 + mi * 16 + ((lane >> 3) & 1) * 8 + (lane & 7);
                int g = ks * 2 + (lane >> 4);
                ldmat_x4(a[mi], AsB + (unsigned)(r * 32 + ((g ^ (r & 7)) << 2)) * 4u);
            }
#pragma unroll
            for (int p = 0; p < 2; p++) {
                int r = wn * 32 + p * 16 + (lane >> 4) * 8 + (lane & 7);
                int g = ks * 2 + ((lane >> 3) & 1);
                unsigned t[4];
                ldmat_x4(t, WsB + (unsigned)(r * 32 + ((g ^ (r & 7)) << 2)) * 4u);
                b[p * 2 + 0][0] = t[0]; b[p * 2 + 0][1] = t[1];
                b[p * 2 + 1][0] = t[2]; b[p * 2 + 1][1] = t[3];
            }
#pragma unroll
            for (int mi = 0; mi < 4; mi++)
#pragma unroll
                for (int ni = 0; ni < 4; ni++)
                    mma_tf32(c[mi][ni], a[mi], b[ni][0], b[ni][1]);
        }
    }

#pragma unroll
    for (int mi = 0; mi < 4; mi++) {
        int r = m0 + wm * 64 + mi * 16 + (lane >> 2);
#pragma unroll
        for (int ni = 0; ni < 4; ni++) {
            int col = n0 + wn * 32 + ni * 8 + (lane & 3) * 2;
            float2 bv = *(const float2*)&bias[col];
            float2 o0 = { c[mi][ni][0] + bv.x, c[mi][ni][1] + bv.y };
            float2 o1 = { c[mi][ni][2] + bv.x, c[mi][ni][3] + bv.y };
            *(float2*)&C[(size_t)r * HH + col]       = o0;
            *(float2*)&C[(size_t)(r + 8) * HH + col] = o1;
        }
    }
}

// ---------------- phase 2: persistent recurrent scan (tf32 mma) ----------
// 128 CTAs = 32 H-tiles (32 cols) x 4 B-tiles (16 rows). W_hh slice resident
// in smem. 8 warps = 2 n-halves x 4-way split-K.
// Sync: per-bt-group counters split 4 ways (8 CTAs/word), release-add arrival,
// single-thread acquire poll over the 4 words.
__global__ void __launch_bounds__(RNN_THREADS, 1) rnn_scan_mma(
    const float* __restrict__ W_hh,
    const float* __restrict__ b_hh,
    float* __restrict__ out)
{
    extern __shared__ unsigned smbuf[];
    unsigned* Wt = smbuf;             // [32][1024] tf32 swizzled (n-major)
    unsigned* Ht = smbuf + 32 * 1024; // [16][1024] tf32 swizzled
    float* red = (float*)(smbuf + 48 * 1024); // [4][16*33] split-K partials

    const int tid  = threadIdx.x;
    const int lane = tid & 31;
    const int warp = tid >> 5;
    const int nf2  = warp & 1;   // n half: cols 0-15 / 16-31
    const int kq   = warp >> 1;  // k quarter: 256 k each
    const int bid  = blockIdx.x;
    const int ht   = bid & 31;
    const int bt   = bid >> 5;

    const unsigned HtB = (unsigned)__cvta_generic_to_shared(Ht);
    const unsigned WtB = (unsigned)__cvta_generic_to_shared(Wt);

    // ---- load W_hh slice ----
#pragma unroll
    for (int i = 0; i < 32; i++) {
        float4 v = *(const float4*)(W_hh + (((size_t)(ht * 32 + i)) << 10) + tid * 4);
        uint4 u = { f2tf32(v.x), f2tf32(v.y), f2tf32(v.z), f2tf32(v.w) };
        *(uint4*)&Wt[i * 1024 + ((tid ^ (i & 7)) << 2)] = u;
    }

    // ---- mma fragment constants ----
    const int rowb = lane >> 2;
    const int colb = nf2 * 16 + 2 * (lane & 3);
    const int kg0  = kq << 6;

    // ---- per-thread epilogue constants (2 adjacent outputs/thread) ----
    const int erow = tid >> 4;
    const int ecol = (2 * tid) & 31;
    const int gb   = bt * 16 + erow;
    const int gc   = ht * 32 + ecol;
    const float2 bh = *(const float2*)&b_hh[gc];
    float* oPtr = out + (size_t)gb * TT * HH + gc;
    float* hOutBase0 = &g_h[1][(size_t)gb * HH + gc];  // written at even t
    float* hOutBase1 = &g_h[0][(size_t)gb * HH + gc];  // written at odd t
    unsigned* myCnt = &g_cnt[bt][ht & 3][0];
    const unsigned* c0p = &g_cnt[bt][0][0];
    const unsigned* c1p = &g_cnt[bt][1][0];
    const unsigned* c2p = &g_cnt[bt][2][0];
    const unsigned* c3p = &g_cnt[bt][3][0];

    for (int t = 0; t < TT; ++t) {
        const int cur = t & 1;
        const float* hsrc = &g_h[cur][(size_t)bt * 16 * HH];

        // ---- xp prefetch (independent of h; hides DRAM under the wait) ----
        float2 xp = __ldcg((const float2*)(oPtr + (size_t)t * HH));

        // ---- group barrier: single-thread acquire poll on 4 sub-counters ----
        if (t > 0) {
            if (tid == 0) {
                const unsigned target = 8u * (unsigned)t;
                while (true) {
                    unsigned v0 = ld_acq(c0p);
                    unsigned v1 = ld_acq(c1p);
                    unsigned v2 = ld_acq(c2p);
                    unsigned v3 = ld_acq(c3p);
                    if (v0 >= target && v1 >= target && v2 >= target && v3 >= target)
                        break;
                }
            }
            __syncthreads();
        }

        // ---- stage h_{t-1} tile (already tf32 bits; pure copy + swizzle) ----
#pragma unroll
        for (int i = 0; i < 16; i++) {
            float4 v = __ldcg((const float4*)(hsrc + ((size_t)i << 10) + tid * 4));
            *(float4*)&Ht[i * 1024 + ((tid ^ (i & 7)) << 2)] = v;
        }
        __syncthreads();

        // ---- mma over this warp's 256-k quarter, 2 n-frags ----
        float c[2][2][4] = {};
#pragma unroll 4
        for (int s2 = 0; s2 < 16; s2++) {
            int g0 = kg0 + s2 * 4;
            unsigned a0[4], a1[4], b0[4], b1[4];
            {
                int r = (lane & 7) + ((lane >> 3) & 1) * 8;
                int g = g0 + (lane >> 4);
                ldmat_x4(a0, HtB + (unsigned)(r * 1024 + ((g ^ (r & 7)) << 2)) * 4u);
                g += 2;
                ldmat_x4(a1, HtB + (unsigned)(r * 1024 + ((g ^ (r & 7)) << 2)) * 4u);
            }
            {
                int r = nf2 * 16 + (lane & 7);
                int g = g0 + (lane >> 3);
                ldmat_x4(b0, WtB + (unsigned)(r * 1024 + ((g ^ (r & 7)) << 2)) * 4u);
                int r2 = r + 8;
                ldmat_x4(b1, WtB + (unsigned)(r2 * 1024 + ((g ^ (r2 & 7)) << 2)) * 4u);
            }
            mma_tf32(c[0][0], a0, b0[0], b0[1]);
            mma_tf32(c[0][1], a0, b1[0], b1[1]);
            mma_tf32(c[1][0], a1, b0[2], b0[3]);
            mma_tf32(c[1][1], a1, b1[2], b1[3]);
        }

        // ---- every warp dumps partials; all 256 threads reduce ----
#pragma unroll
        for (int ni = 0; ni < 2; ni++) {
#pragma unroll
            for (int half = 0; half < 2; half++) {
                int r = rowb + 8 * half;
                int cc = colb + ni * 8;
                red[kq * 528 + r * 33 + cc]     = c[0][ni][half * 2]     + c[1][ni][half * 2];
                red[kq * 528 + r * 33 + cc + 1] = c[0][ni][half * 2 + 1] + c[1][ni][half * 2 + 1];
            }
        }
        __syncthreads();

        float s0 = xp.x + bh.x;
        float s1 = xp.y + bh.y;
#pragma unroll
        for (int q = 0; q < 4; q++) {
            s0 += red[q * 528 + erow * 33 + ecol];
            s1 += red[q * 528 + erow * 33 + ecol + 1];
        }
        float2 hv = { tanhf(s0), tanhf(s1) };

        *(float2*)(oPtr + (size_t)t * HH) = hv;
        float2 hs = { __uint_as_float(f2tf32(hv.x)), __uint_as_float(f2tf32(hv.y)) };
        __stcg((float2*)(cur ? hOutBase1 : hOutBase0), hs);

        // ---- arrival: release-add on this CTA's sub-counter after drain ----
        __syncthreads();
        if (tid == 0)
            asm volatile("red.release.gpu.global.add.u32 [%0], 1;" :: "l"(myCnt));
    }
}

// ---------------- launch ----------------
extern "C" void kernel_launch(void* const* d_in, const int* in_sizes, int n_in,
                              void* d_out, int out_size) {
    const float* x    = (const float*)d_in[0];
    const float* h0   = (const float*)d_in[1];
    const float* W_ih = (const float*)d_in[2];
    const float* b_ih = (const float*)d_in[3];
    const float* W_hh = (const float*)d_in[4];
    const float* b_hh = (const float*)d_in[5];
    float* out = (float*)d_out;

    init_kernel<<<(BB * HH + 255) / 256, 256>>>(h0);

    dim3 g1(HH / 128, (BB * TT) / 128);
    gemm_xw_mma<<<g1, 256>>>(x, W_ih, b_ih, out);

    const int smem_bytes = (48 * 1024) * 4 + 4 * 528 * 4;  // 205056 B
    cudaFuncSetAttribute(rnn_scan_mma,
                         cudaFuncAttributeMaxDynamicSharedMemorySize, smem_bytes);
    rnn_scan_mma<<<NB_CTAS, RNN_THREADS, smem_bytes>>>(W_hh, b_hh, out);
}

// round 13
// speedup vs baseline: 1.7345x; 1.2291x over previous
#include <cuda_runtime.h>
#include <math.h>

// Problem constants
#define BB 64
#define TT 512
#define II 1024
#define HH 1024

#define NB_CTAS 128
#define RNN_THREADS 256

// ---------------- device scratch ----------------
__device__ float g_h[2][BB * HH];                     // ping-pong hidden state (tf32-rounded bits)
__device__ __align__(512) unsigned g_cnt[4 * 32];     // per-bt-group counters (128B apart)

// ---------------- helpers ----------------
__device__ __forceinline__ unsigned f2tf32(float x) {
    unsigned r;
    asm("cvt.rna.tf32.f32 %0, %1;" : "=r"(r) : "f"(x));
    return r;
}

__device__ __forceinline__ void ldmat_x4(unsigned* r, unsigned addr) {
    asm volatile("ldmatrix.sync.aligned.m8n8.x4.shared.b16 {%0,%1,%2,%3}, [%4];"
                 : "=r"(r[0]), "=r"(r[1]), "=r"(r[2]), "=r"(r[3]) : "r"(addr));
}

__device__ __forceinline__ void mma_tf32(float* c, const unsigned* a, unsigned b0, unsigned b1) {
    asm volatile(
        "mma.sync.aligned.m16n8k8.row.col.f32.tf32.tf32.f32 "
        "{%0,%1,%2,%3},{%4,%5,%6,%7},{%8,%9},{%0,%1,%2,%3};"
        : "+f"(c[0]), "+f"(c[1]), "+f"(c[2]), "+f"(c[3])
        : "r"(a[0]), "r"(a[1]), "r"(a[2]), "r"(a[3]), "r"(b0), "r"(b1));
}

// ---------------- init ----------------
__global__ void init_kernel(const float* __restrict__ h0) {
    int i = blockIdx.x * blockDim.x + threadIdx.x;
    if (i < BB * HH) g_h[0][i] = __uint_as_float(f2tf32(h0[i]));  // pre-rounded tf32 bits
    if (i < 128) g_cnt[i] = 0u;
}

// ---------------- phase 1: xp = x @ W_ih^T + b_ih  (tf32 mma) -------------
// CTA tile 128(M) x 128(N), k-chunk 32. 8 warps (2m x 4n), warp tile 64x32.
__global__ void __launch_bounds__(256) gemm_xw_mma(
    const float* __restrict__ A,    // x [M][K]
    const float* __restrict__ W,    // W_ih [N][K]
    const float* __restrict__ bias, // [N]
    float* __restrict__ C)          // [M][N]
{
    __shared__ unsigned As[128 * 32];
    __shared__ unsigned Ws[128 * 32];

    const int tid  = threadIdx.x;
    const int lane = tid & 31;
    const int warp = tid >> 5;
    const int wm   = warp & 1;   // 0..1
    const int wn   = warp >> 1;  // 0..3
    const int n0   = blockIdx.x * 128;
    const int m0   = blockIdx.y * 128;

    const unsigned AsB = (unsigned)__cvta_generic_to_shared(As);
    const unsigned WsB = (unsigned)__cvta_generic_to_shared(Ws);

    float c[4][4][4] = {};

    int lr[4], lg[4];
    size_t aoff[4], woff[4];
#pragma unroll
    for (int i = 0; i < 4; i++) {
        int idx = tid + i * 256;
        lr[i] = idx >> 3;
        lg[i] = idx & 7;
        aoff[i] = (size_t)(m0 + lr[i]) * II + lg[i] * 4;
        woff[i] = (size_t)(n0 + lr[i]) * II + lg[i] * 4;
    }

    float4 ra[4], rw[4];
#pragma unroll
    for (int i = 0; i < 4; i++) {
        ra[i] = *(const float4*)(A + aoff[i]);
        rw[i] = *(const float4*)(W + woff[i]);
    }

    for (int kc = 0; kc < 32; kc++) {
        __syncthreads();
#pragma unroll
        for (int i = 0; i < 4; i++) {
            uint4 ua = { f2tf32(ra[i].x), f2tf32(ra[i].y), f2tf32(ra[i].z), f2tf32(ra[i].w) };
            uint4 uw = { f2tf32(rw[i].x), f2tf32(rw[i].y), f2tf32(rw[i].z), f2tf32(rw[i].w) };
            int off = lr[i] * 32 + ((lg[i] ^ (lr[i] & 7)) << 2);
            *(uint4*)&As[off] = ua;
            *(uint4*)&Ws[off] = uw;
        }
        __syncthreads();

        if (kc + 1 < 32) {
            int k0 = (kc + 1) * 32;
#pragma unroll
            for (int i = 0; i < 4; i++) {
                ra[i] = *(const float4*)(A + aoff[i] + k0);
                rw[i] = *(const float4*)(W + woff[i] + k0);
            }
        }

#pragma unroll
        for (int ks = 0; ks < 4; ks++) {
            unsigned a[4][4], b[4][2];
#pragma unroll
            for (int mi = 0; mi < 4; mi++) {
                int r = wm * 64 + mi * 16 + ((lane >> 3) & 1) * 8 + (lane & 7);
                int g = ks * 2 + (lane >> 4);
                ldmat_x4(a[mi], AsB + (unsigned)(r * 32 + ((g ^ (r & 7)) << 2)) * 4u);
            }
#pragma unroll
            for (int p = 0; p < 2; p++) {
                int r = wn * 32 + p * 16 + (lane >> 4) * 8 + (lane & 7);
                int g = ks * 2 + ((lane >> 3) & 1);
                unsigned t[4];
                ldmat_x4(t, WsB + (unsigned)(r * 32 + ((g ^ (r & 7)) << 2)) * 4u);
                b[p * 2 + 0][0] = t[0]; b[p * 2 + 0][1] = t[1];
                b[p * 2 + 1][0] = t[2]; b[p * 2 + 1][1] = t[3];
            }
#pragma unroll
            for (int mi = 0; mi < 4; mi++)
#pragma unroll
                for (int ni = 0; ni < 4; ni++)
                    mma_tf32(c[mi][ni], a[mi], b[ni][0], b[ni][1]);
        }
    }

#pragma unroll
    for (int mi = 0; mi < 4; mi++) {
        int r = m0 + wm * 64 + mi * 16 + (lane >> 2);
#pragma unroll
        for (int ni = 0; ni < 4; ni++) {
            int col = n0 + wn * 32 + ni * 8 + (lane & 3) * 2;
            float2 bv = *(const float2*)&bias[col];
            float2 o0 = { c[mi][ni][0] + bv.x, c[mi][ni][1] + bv.y };
            float2 o1 = { c[mi][ni][2] + bv.x, c[mi][ni][3] + bv.y };
            *(float2*)&C[(size_t)r * HH + col]       = o0;
            *(float2*)&C[(size_t)(r + 8) * HH + col] = o1;
        }
    }
}

// ---------------- phase 2: persistent recurrent scan (tf32 mma) ----------
// 128 CTAs = 32 H-tiles (32 cols) x 4 B-tiles (16 rows). W_hh slice resident
// in smem. 8 warps = 2 n-halves x 4-way split-K.
// Sync: per-bt-group single atomic counter (R8-proven), release-add arrival,
// single-thread acquire poll. h stored pre-rounded to tf32 bits -> staging
// is a pure copy (no cvt on the critical path).
__global__ void __launch_bounds__(RNN_THREADS, 1) rnn_scan_mma(
    const float* __restrict__ W_hh,
    const float* __restrict__ b_hh,
    float* __restrict__ out)
{
    extern __shared__ unsigned smbuf[];
    unsigned* Wt = smbuf;             // [32][1024] tf32 swizzled (n-major)
    unsigned* Ht = smbuf + 32 * 1024; // [16][1024] tf32 swizzled
    float* red = (float*)(smbuf + 48 * 1024); // [4][16*33] split-K partials

    const int tid  = threadIdx.x;
    const int lane = tid & 31;
    const int warp = tid >> 5;
    const int nf2  = warp & 1;   // n half: cols 0-15 / 16-31
    const int kq   = warp >> 1;  // k quarter: 256 k each
    const int bid  = blockIdx.x;
    const int ht   = bid & 31;
    const int bt   = bid >> 5;

    const unsigned HtB = (unsigned)__cvta_generic_to_shared(Ht);
    const unsigned WtB = (unsigned)__cvta_generic_to_shared(Wt);

    // ---- load W_hh slice ----
#pragma unroll
    for (int i = 0; i < 32; i++) {
        float4 v = *(const float4*)(W_hh + (((size_t)(ht * 32 + i)) << 10) + tid * 4);
        uint4 u = { f2tf32(v.x), f2tf32(v.y), f2tf32(v.z), f2tf32(v.w) };
        *(uint4*)&Wt[i * 1024 + ((tid ^ (i & 7)) << 2)] = u;
    }

    // ---- mma fragment constants ----
    const int rowb = lane >> 2;
    const int colb = nf2 * 16 + 2 * (lane & 3);
    const int kg0  = kq << 6;

    // ---- per-thread epilogue constants (2 adjacent outputs/thread) ----
    const int erow = tid >> 4;
    const int ecol = (2 * tid) & 31;
    const int gb   = bt * 16 + erow;
    const int gc   = ht * 32 + ecol;
    const float2 bh = *(const float2*)&b_hh[gc];
    float* oPtr = out + (size_t)gb * TT * HH + gc;
    float* hOutBase0 = &g_h[1][(size_t)gb * HH + gc];  // written at even t
    float* hOutBase1 = &g_h[0][(size_t)gb * HH + gc];  // written at odd t
    unsigned* cnt = &g_cnt[bt * 32];

    for (int t = 0; t < TT; ++t) {
        const int cur = t & 1;
        const float* hsrc = &g_h[cur][(size_t)bt * 16 * HH];

        // ---- xp prefetch (independent of h; hides DRAM under the wait) ----
        float2 xp = __ldcg((const float2*)(oPtr + (size_t)t * HH));

        // ---- group barrier: single-thread acquire poll on group counter ----
        if (t > 0) {
            if (tid == 0) {
                const unsigned target = 32u * (unsigned)t;
                unsigned v;
                do {
                    asm volatile("ld.acquire.gpu.global.u32 %0, [%1];"
                                 : "=r"(v) : "l"(cnt));
                } while (v < target);
            }
            __syncthreads();
        }

        // ---- stage h_{t-1} tile (already tf32 bits; pure copy + swizzle) ----
#pragma unroll
        for (int i = 0; i < 16; i++) {
            float4 v = __ldcg((const float4*)(hsrc + ((size_t)i << 10) + tid * 4));
            *(float4*)&Ht[i * 1024 + ((tid ^ (i & 7)) << 2)] = v;
        }
        __syncthreads();

        // ---- mma over this warp's 256-k quarter, 2 n-frags ----
        float c[2][2][4] = {};
#pragma unroll 4
        for (int s2 = 0; s2 < 16; s2++) {
            int g0 = kg0 + s2 * 4;
            unsigned a0[4], a1[4], b0[4], b1[4];
            {
                int r = (lane & 7) + ((lane >> 3) & 1) * 8;
                int g = g0 + (lane >> 4);
                ldmat_x4(a0, HtB + (unsigned)(r * 1024 + ((g ^ (r & 7)) << 2)) * 4u);
                g += 2;
                ldmat_x4(a1, HtB + (unsigned)(r * 1024 + ((g ^ (r & 7)) << 2)) * 4u);
            }
            {
                int r = nf2 * 16 + (lane & 7);
                int g = g0 + (lane >> 3);
                ldmat_x4(b0, WtB + (unsigned)(r * 1024 + ((g ^ (r & 7)) << 2)) * 4u);
                int r2 = r + 8;
                ldmat_x4(b1, WtB + (unsigned)(r2 * 1024 + ((g ^ (r2 & 7)) << 2)) * 4u);
            }
            mma_tf32(c[0][0], a0, b0[0], b0[1]);
            mma_tf32(c[0][1], a0, b1[0], b1[1]);
            mma_tf32(c[1][0], a1, b0[2], b0[3]);
            mma_tf32(c[1][1], a1, b1[2], b1[3]);
        }

        // ---- every warp dumps partials; all 256 threads reduce ----
#pragma unroll
        for (int ni = 0; ni < 2; ni++) {
#pragma unroll
            for (int half = 0; half < 2; half++) {
                int r = rowb + 8 * half;
                int cc = colb + ni * 8;
                red[kq * 528 + r * 33 + cc]     = c[0][ni][half * 2]     + c[1][ni][half * 2];
                red[kq * 528 + r * 33 + cc + 1] = c[0][ni][half * 2 + 1] + c[1][ni][half * 2 + 1];
            }
        }
        __syncthreads();

        float s0 = xp.x + bh.x;
        float s1 = xp.y + bh.y;
#pragma unroll
        for (int q = 0; q < 4; q++) {
            s0 += red[q * 528 + erow * 33 + ecol];
            s1 += red[q * 528 + erow * 33 + ecol + 1];
        }
        float2 hv = { tanhf(s0), tanhf(s1) };

        *(float2*)(oPtr + (size_t)t * HH) = hv;
        float2 hs = { __uint_as_float(f2tf32(hv.x)), __uint_as_float(f2tf32(hv.y)) };
        __stcg((float2*)(cur ? hOutBase1 : hOutBase0), hs);

        // ---- arrival: release-add on group counter after CTA-wide drain ----
        __syncthreads();
        if (tid == 0)
            asm volatile("red.release.gpu.global.add.u32 [%0], 1;" :: "l"(cnt));
    }
}

// ---------------- launch ----------------
extern "C" void kernel_launch(void* const* d_in, const int* in_sizes, int n_in,
                              void* d_out, int out_size) {
    const float* x    = (const float*)d_in[0];
    const float* h0   = (const float*)d_in[1];
    const float* W_ih = (const float*)d_in[2];
    const float* b_ih = (const float*)d_in[3];
    const float* W_hh = (const float*)d_in[4];
    const float* b_hh = (const float*)d_in[5];
    float* out = (float*)d_out;

    init_kernel<<<(BB * HH + 255) / 256, 256>>>(h0);

    dim3 g1(HH / 128, (BB * TT) / 128);
    gemm_xw_mma<<<g1, 256>>>(x, W_ih, b_ih, out);

    const int smem_bytes = (48 * 1024) * 4 + 4 * 528 * 4;  // 205056 B
    cudaFuncSetAttribute(rnn_scan_mma,
                         cudaFuncAttributeMaxDynamicSharedMemorySize, smem_bytes);
    rnn_scan_mma<<<NB_CTAS, RNN_THREADS, smem_bytes>>>(W_hh, b_hh, out);
}